// round 9
// baseline (speedup 1.0000x reference)
#include <cuda_runtime.h>
#include <cuda_fp16.h>

#define NN 100000
#define NE 1600000

// Scratch slots, each NN*64 floats (25.6MB): 0..3
// slot 2 is reused as fp16 payload storage (NN rows x 64 halves = 128B/row).
__device__ float g_scratch[4ull * NN * 64];
__device__ int g_deg[NN];   // zero-init; reset by final_kernel each launch
__device__ int g_src[NE];
__device__ int g_dst[NE];

// A_j = sum_s COEF[s][j] * Wm1_s  (THETAS for D=2 folded)
__constant__ float COEF[3][3] = {
    {3.0f,  0.0f,  0.0f},
    {-3.0f, 3.0f,  0.0f},
    {0.75f, -1.5f, 0.75f}
};

__device__ __forceinline__ float* slot(int s) {
    return g_scratch + (size_t)s * (NN * 64);
}

__device__ __forceinline__ float dinv_of(int node) {
    int d = g_deg[node];
    return rsqrtf((float)(d > 0 ? d : 1));
}

// pack 4 floats -> 4 halves (uint2)
__device__ __forceinline__ uint2 pack_half4(float a, float b, float c, float d) {
    __half2 h0 = __floats2half2_rn(a, b);
    __half2 h1 = __floats2half2_rn(c, d);
    uint2 r;
    r.x = *(unsigned*)&h0;
    r.y = *(unsigned*)&h1;
    return r;
}

// ---------------------------------------------------------------------------
// Convert edge_index to int32 src/dst AND count in-degrees, one pass.
// Per-block dtype detect: int64 data has all high halves zero (indices < 1e5).
__global__ void convert_count_kernel(const void* ei) {
    __shared__ int s_is64;
    if (threadIdx.x == 0) {
        const unsigned long long* p = (const unsigned long long*)ei;
        int is64 = 1;
        for (int k = 0; k < 64; k++)
            if ((p[k] >> 32) != 0ull) { is64 = 0; break; }
        s_is64 = is64;
    }
    __syncthreads();
    int e = blockIdx.x * 256 + threadIdx.x;
    if (e < NE) {
        int s, d;
        if (s_is64) {
            const long long* p = (const long long*)ei;
            s = (int)p[e]; d = (int)p[NE + e];
        } else {
            const int* p = (const int*)ei;
            s = p[e]; d = p[NE + e];
        }
        g_src[e] = s;
        g_dst[e] = d;
        atomicAdd(&g_deg[d], 1);
    }
}

// ---------------------------------------------------------------------------
// Mainloop: 4 rows (float4 over k) x 4 cols, k grouped by 4.
// xs: [row][k] natural layout, stride 68 (conflict-free float4 staging).
__device__ __forceinline__ void mma_chunk64(
    const float* xs, const float* ws, int tx, int ty, float acc[4][4]) {
#pragma unroll
    for (int k4 = 0; k4 < 16; k4++) {
        float4 a0 = *(const float4*)&xs[(ty * 4 + 0) * 68 + k4 * 4];
        float4 a1 = *(const float4*)&xs[(ty * 4 + 1) * 68 + k4 * 4];
        float4 a2 = *(const float4*)&xs[(ty * 4 + 2) * 68 + k4 * 4];
        float4 a3 = *(const float4*)&xs[(ty * 4 + 3) * 68 + k4 * 4];
        float r0[4] = {a0.x, a0.y, a0.z, a0.w};
        float r1[4] = {a1.x, a1.y, a1.z, a1.w};
        float r2[4] = {a2.x, a2.y, a2.z, a2.w};
        float r3[4] = {a3.x, a3.y, a3.z, a3.w};
#pragma unroll
        for (int j = 0; j < 4; j++) {
            float4 b = *(const float4*)&ws[(k4 * 4 + j) * 64 + tx * 4];
            acc[0][0] += r0[j] * b.x; acc[0][1] += r0[j] * b.y;
            acc[0][2] += r0[j] * b.z; acc[0][3] += r0[j] * b.w;
            acc[1][0] += r1[j] * b.x; acc[1][1] += r1[j] * b.y;
            acc[1][2] += r1[j] * b.z; acc[1][3] += r1[j] * b.w;
            acc[2][0] += r2[j] * b.x; acc[2][1] += r2[j] * b.y;
            acc[2][2] += r2[j] * b.z; acc[2][3] += r2[j] * b.w;
            acc[3][0] += r3[j] * b.x; acc[3][1] += r3[j] * b.y;
            acc[3][2] += r3[j] * b.z; acc[3][3] += r3[j] * b.w;
        }
    }
}

// ---------------------------------------------------------------------------
// Y[N,64] = relu(X[N,K] @ W[K,64] + B), K in {64,128}
// WRITE_G: also write G = Y * dinv as fp16 (slot 2) and zero msg (slot 3).
template <int K, bool WRITE_G>
__global__ __launch_bounds__(256)
void gemm_relu_kernel(const float* __restrict__ Xext, int xslot,
                      const float* __restrict__ W, const float* __restrict__ B,
                      int yslot) {
    const float* X = Xext ? Xext : slot(xslot);
    float* Y = slot(yslot);

    __shared__ float xs[64 * 68];  // natural: xs[row][k], stride 68
    __shared__ float ws[64 * 64];  // ws[k][col]

    int tid = threadIdx.x;
    int tx = tid & 15, ty = tid >> 4;
    int nodeBase = blockIdx.x * 64;

    float acc[4][4];
#pragma unroll
    for (int i = 0; i < 4; i++)
#pragma unroll
        for (int j = 0; j < 4; j++) acc[i][j] = 0.0f;

    for (int kc = 0; kc < K; kc += 64) {
#pragma unroll
        for (int i = 0; i < 4; i++) {
            int p = i * 256 + tid;
            int r = p >> 4;
            int c4 = p & 15;
            int node = nodeBase + r;
            float4 v = make_float4(0.f, 0.f, 0.f, 0.f);
            if (node < NN)
                v = *(const float4*)(X + (size_t)node * K + kc + c4 * 4);
            *(float4*)&xs[r * 68 + c4 * 4] = v;
        }
#pragma unroll
        for (int i = 0; i < 4; i++) {
            int p = i * 256 + tid;
            ((float4*)ws)[p] =
                *(const float4*)(W + (size_t)(kc + (p >> 4)) * 64 + (p & 15) * 4);
        }
        __syncthreads();
        mma_chunk64(xs, ws, tx, ty, acc);
        __syncthreads();
    }

    float4 bb = *(const float4*)&B[tx * 4];
#pragma unroll
    for (int i = 0; i < 4; i++) {
        int node = nodeBase + ty * 4 + i;
        if (node < NN) {
            float4 o;
            o.x = fmaxf(acc[i][0] + bb.x, 0.0f);
            o.y = fmaxf(acc[i][1] + bb.y, 0.0f);
            o.z = fmaxf(acc[i][2] + bb.z, 0.0f);
            o.w = fmaxf(acc[i][3] + bb.w, 0.0f);
            *(float4*)(Y + (size_t)node * 64 + tx * 4) = o;
            if (WRITE_G) {
                float di = dinv_of(node);
                uint2* gh = (uint2*)slot(2);  // 16 uint2 (64 halves) per row
                gh[(size_t)node * 16 + tx] =
                    pack_half4(o.x * di, o.y * di, o.z * di, o.w * di);
                *(float4*)(slot(3) + (size_t)node * 64 + tx * 4) =
                    make_float4(0.f, 0.f, 0.f, 0.f);
            }
        }
    }
}

// ---------------------------------------------------------------------------
// msg[dst] += g[src] over all edges. 8 lanes per edge: each lane reads 8
// halves (16B), converts, and does two float4 REDs.
__global__ __launch_bounds__(256)
void scatter_kernel() {
    const uint4* gh = (const uint4*)slot(2);  // 8 uint4 per row (128B)
    float4* msg = (float4*)slot(3);

    int t = blockIdx.x * 256 + threadIdx.x;
    int e = t >> 3;              // grid sized exactly: e < NE always
    int lane = threadIdx.x & 7;

    int s = g_src[e];
    int d = g_dst[e];

    uint4 h = gh[(size_t)s * 8 + lane];
    float2 p0 = __half22float2(*(__half2*)&h.x);
    float2 p1 = __half22float2(*(__half2*)&h.y);
    float2 p2 = __half22float2(*(__half2*)&h.z);
    float2 p3 = __half22float2(*(__half2*)&h.w);
    float4 v0 = make_float4(p0.x, p0.y, p1.x, p1.y);
    float4 v1 = make_float4(p2.x, p2.y, p3.x, p3.y);

    atomicAdd(&msg[(size_t)d * 16 + lane * 2 + 0], v0);
    atomicAdd(&msg[(size_t)d * 16 + lane * 2 + 1], v1);
}

// ---------------------------------------------------------------------------
// f1 = f0 - msg*dinv ; g(half) = f1*dinv ; msg = 0
__global__ __launch_bounds__(256)
void update_kernel(int f0slot, int msgslot, int f1slot) {
    int i = blockIdx.x * 256 + threadIdx.x;
    if (i < NN * 16) {
        const float4* f0 = (const float4*)slot(f0slot);
        float4* msg = (float4*)slot(msgslot);
        float4* f1 = (float4*)slot(f1slot);
        uint2* gh = (uint2*)slot(2);
        float di = dinv_of(i >> 4);
        float4 a = f0[i], m = msg[i];
        float4 f;
        f.x = a.x - m.x * di;
        f.y = a.y - m.y * di;
        f.z = a.z - m.z * di;
        f.w = a.w - m.w * di;
        f1[i] = f;
        gh[i] = pack_half4(f.x * di, f.y * di, f.z * di, f.w * di);
        msg[i] = make_float4(0.f, 0.f, 0.f, 0.f);
    }
}

// ---------------------------------------------------------------------------
// Final: f2 = f1 - msg*dinv (on the fly); hf = relu(sum_j f_j @ A_j + bm1);
// out = hf @ Wm2 + bm2. Also resets g_deg to 0 for the next graph replay.
__global__ __launch_bounds__(256)
void final_kernel(int f0slot, int f1slot, int msgslot,
                  const float* __restrict__ Wm1, const float* __restrict__ bm1,
                  const float* __restrict__ Wm2, const float* __restrict__ bm2,
                  float* __restrict__ out) {
    const float4* f0 = (const float4*)slot(f0slot);
    const float4* f1 = (const float4*)slot(f1slot);
    const float4* msg = (const float4*)slot(msgslot);

    __shared__ float fs[64 * 68];  // natural [node][k]; reused as hf[node][col]
    __shared__ float as[64 * 64];  // A_j[k][col]
    __shared__ float wm2s[128];

    int tid = threadIdx.x;
    int tx = tid & 15, ty = tid >> 4;
    int nodeBase = blockIdx.x * 64;

    if (tid < 128) wm2s[tid] = Wm2[tid];

    float acc[4][4];
#pragma unroll
    for (int i = 0; i < 4; i++)
#pragma unroll
        for (int j = 0; j < 4; j++) acc[i][j] = 0.0f;

    const float4* Wm1_4 = (const float4*)Wm1;

    for (int j = 0; j < 3; j++) {
        float c0 = COEF[j][0], c1 = COEF[j][1], c2 = COEF[j][2];
        // build A_j (64x64) in smem
#pragma unroll
        for (int i = 0; i < 4; i++) {
            int p = i * 256 + tid;  // p = k*16 + c4
            float4 w0 = Wm1_4[p];
            float4 w1 = Wm1_4[1024 + p];
            float4 w2 = Wm1_4[2048 + p];
            float4 a;
            a.x = c0 * w0.x + c1 * w1.x + c2 * w2.x;
            a.y = c0 * w0.y + c1 * w1.y + c2 * w2.y;
            a.z = c0 * w0.z + c1 * w1.z + c2 * w2.z;
            a.w = c0 * w0.w + c1 * w1.w + c2 * w2.w;
            ((float4*)as)[p] = a;
        }
        // stage f_j natural [node][k]
#pragma unroll
        for (int i = 0; i < 4; i++) {
            int p = i * 256 + tid;
            int r = p >> 4, c4 = p & 15;
            int node = nodeBase + r;
            float4 v = make_float4(0.f, 0.f, 0.f, 0.f);
            if (node < NN) {
                int idx = node * 16 + c4;
                if (j == 0) {
                    v = f0[idx];
                } else if (j == 1) {
                    v = f1[idx];
                } else {
                    float4 a1 = f1[idx], m = msg[idx];
                    float di = dinv_of(node);
                    v.x = a1.x - m.x * di;
                    v.y = a1.y - m.y * di;
                    v.z = a1.z - m.z * di;
                    v.w = a1.w - m.w * di;
                }
            }
            *(float4*)&fs[r * 68 + c4 * 4] = v;
        }
        __syncthreads();
        mma_chunk64(fs, as, tx, ty, acc);
        __syncthreads();
    }

    // bias + relu -> store hf into fs as [node][col], stride 68
    float4 bb = *(const float4*)&bm1[tx * 4];
#pragma unroll
    for (int i = 0; i < 4; i++) {
        int r = ty * 4 + i;
        float4 o;
        o.x = fmaxf(acc[i][0] + bb.x, 0.0f);
        o.y = fmaxf(acc[i][1] + bb.y, 0.0f);
        o.z = fmaxf(acc[i][2] + bb.z, 0.0f);
        o.w = fmaxf(acc[i][3] + bb.w, 0.0f);
        *(float4*)&fs[r * 68 + tx * 4] = o;
    }

    // reset degree counters for the next launch/replay (64 nodes per block)
    if (tid < 64) {
        int node = nodeBase + tid;
        if (node < NN) g_deg[node] = 0;
    }
    __syncthreads();

    // out[n][c] = bm2[c] + sum_k hf[n][k] * Wm2[k][c]
    if (tid < 128) {
        int n = tid >> 1, c = tid & 1;
        int node = nodeBase + n;
        if (node < NN) {
            float s = bm2[c];
#pragma unroll
            for (int k = 0; k < 64; k++) s += fs[n * 68 + k] * wm2s[k * 2 + c];
            out[(size_t)node * 2 + c] = s;
        }
    }
}

// ---------------------------------------------------------------------------
extern "C" void kernel_launch(void* const* d_in, const int* in_sizes, int n_in,
                              void* d_out, int out_size) {
    const float* x = (const float*)d_in[0];
    const void* ei = d_in[1];
    const float* W1 = (const float*)d_in[2];
    const float* b1 = (const float*)d_in[3];
    const float* W2 = (const float*)d_in[4];
    const float* b2 = (const float*)d_in[5];
    const float* Wm1 = (const float*)d_in[6];
    const float* bm1 = (const float*)d_in[7];
    const float* Wm2 = (const float*)d_in[8];
    const float* bm2 = (const float*)d_in[9];
    float* out = (float*)d_out;

    int nbe = (NE + 255) / 256;
    int nb = (NN + 63) / 64;   // 1563
    int nv = (NN * 16 + 255) / 256;
    int ns = (NE * 8) / 256;   // 50000 blocks

    convert_count_kernel<<<nbe, 256>>>(ei);                            // 1
    gemm_relu_kernel<128, false><<<nb, 256>>>(x, -1, W1, b1, 0);       // 2
    gemm_relu_kernel<64, true><<<nb, 256>>>(nullptr, 0, W2, b2, 1);    // 3
    scatter_kernel<<<ns, 256>>>();                                     // 4 (profiled)
    update_kernel<<<nv, 256>>>(1, 3, 0);                               // 5
    scatter_kernel<<<ns, 256>>>();                                     // 6
    final_kernel<<<nb, 256>>>(1, 0, 3, Wm1, bm1, Wm2, bm2, out);       // 7
}

// round 12
// speedup vs baseline: 1.0868x; 1.0868x over previous
#include <cuda_runtime.h>
#include <cuda_fp16.h>

#define NN 100000
#define NE 1600000

// Scratch slots, each NN*64 floats (25.6MB): 0..3
// slot 2 is reused as fp16 payload storage (NN rows x 64 halves = 128B/row).
__device__ float g_scratch[4ull * NN * 64];
__device__ int g_deg[NN];   // zero-init; reset by final_kernel each launch
__device__ int g_src[NE];
__device__ int g_dst[NE];

// A_j = sum_s COEF[s][j] * Wm1_s  (THETAS for D=2 folded)
__constant__ float COEF[3][3] = {
    {3.0f,  0.0f,  0.0f},
    {-3.0f, 3.0f,  0.0f},
    {0.75f, -1.5f, 0.75f}
};

__device__ __forceinline__ float* slot(int s) {
    return g_scratch + (size_t)s * (NN * 64);
}

__device__ __forceinline__ float dinv_of(int node) {
    int d = g_deg[node];
    return rsqrtf((float)(d > 0 ? d : 1));
}

// pack 4 floats -> 4 halves (uint2)
__device__ __forceinline__ uint2 pack_half4(float a, float b, float c, float d) {
    __half2 h0 = __floats2half2_rn(a, b);
    __half2 h1 = __floats2half2_rn(c, d);
    uint2 r;
    r.x = *(unsigned*)&h0;
    r.y = *(unsigned*)&h1;
    return r;
}

// ---------------------------------------------------------------------------
// Convert edge_index to int32 src/dst AND count in-degrees, one pass.
// Per-block dtype detect: int64 data has all high halves zero (indices < 1e5).
__global__ void convert_count_kernel(const void* ei) {
    __shared__ int s_is64;
    if (threadIdx.x == 0) {
        const unsigned long long* p = (const unsigned long long*)ei;
        int is64 = 1;
        for (int k = 0; k < 64; k++)
            if ((p[k] >> 32) != 0ull) { is64 = 0; break; }
        s_is64 = is64;
    }
    __syncthreads();
    int e = blockIdx.x * 256 + threadIdx.x;
    if (e < NE) {
        int s, d;
        if (s_is64) {
            const long long* p = (const long long*)ei;
            s = (int)p[e]; d = (int)p[NE + e];
        } else {
            const int* p = (const int*)ei;
            s = p[e]; d = p[NE + e];
        }
        g_src[e] = s;
        g_dst[e] = d;
        atomicAdd(&g_deg[d], 1);
    }
}

// ---------------------------------------------------------------------------
// Mainloop: 4 rows (float4 over k) x 4 cols, k grouped by 4.
// xs: [row][k] natural layout, stride 68 (conflict-free float4 staging).
__device__ __forceinline__ void mma_chunk64(
    const float* xs, const float* ws, int tx, int ty, float acc[4][4]) {
#pragma unroll
    for (int k4 = 0; k4 < 16; k4++) {
        float4 a0 = *(const float4*)&xs[(ty * 4 + 0) * 68 + k4 * 4];
        float4 a1 = *(const float4*)&xs[(ty * 4 + 1) * 68 + k4 * 4];
        float4 a2 = *(const float4*)&xs[(ty * 4 + 2) * 68 + k4 * 4];
        float4 a3 = *(const float4*)&xs[(ty * 4 + 3) * 68 + k4 * 4];
        float r0[4] = {a0.x, a0.y, a0.z, a0.w};
        float r1[4] = {a1.x, a1.y, a1.z, a1.w};
        float r2[4] = {a2.x, a2.y, a2.z, a2.w};
        float r3[4] = {a3.x, a3.y, a3.z, a3.w};
#pragma unroll
        for (int j = 0; j < 4; j++) {
            float4 b = *(const float4*)&ws[(k4 * 4 + j) * 64 + tx * 4];
            acc[0][0] += r0[j] * b.x; acc[0][1] += r0[j] * b.y;
            acc[0][2] += r0[j] * b.z; acc[0][3] += r0[j] * b.w;
            acc[1][0] += r1[j] * b.x; acc[1][1] += r1[j] * b.y;
            acc[1][2] += r1[j] * b.z; acc[1][3] += r1[j] * b.w;
            acc[2][0] += r2[j] * b.x; acc[2][1] += r2[j] * b.y;
            acc[2][2] += r2[j] * b.z; acc[2][3] += r2[j] * b.w;
            acc[3][0] += r3[j] * b.x; acc[3][1] += r3[j] * b.y;
            acc[3][2] += r3[j] * b.z; acc[3][3] += r3[j] * b.w;
        }
    }
}

// ---------------------------------------------------------------------------
// Y[N,64] = relu(X[N,K] @ W[K,64] + B), K in {64,128}
// WRITE_G: also write G = Y * dinv as fp16 (slot 2) and zero msg (slot 3).
template <int K, bool WRITE_G>
__global__ __launch_bounds__(256)
void gemm_relu_kernel(const float* __restrict__ Xext, int xslot,
                      const float* __restrict__ W, const float* __restrict__ B,
                      int yslot) {
    const float* X = Xext ? Xext : slot(xslot);
    float* Y = slot(yslot);

    __shared__ float xs[64 * 68];  // natural: xs[row][k], stride 68
    __shared__ float ws[64 * 64];  // ws[k][col]

    int tid = threadIdx.x;
    int tx = tid & 15, ty = tid >> 4;
    int nodeBase = blockIdx.x * 64;

    float acc[4][4];
#pragma unroll
    for (int i = 0; i < 4; i++)
#pragma unroll
        for (int j = 0; j < 4; j++) acc[i][j] = 0.0f;

    for (int kc = 0; kc < K; kc += 64) {
#pragma unroll
        for (int i = 0; i < 4; i++) {
            int p = i * 256 + tid;
            int r = p >> 4;
            int c4 = p & 15;
            int node = nodeBase + r;
            float4 v = make_float4(0.f, 0.f, 0.f, 0.f);
            if (node < NN)
                v = *(const float4*)(X + (size_t)node * K + kc + c4 * 4);
            *(float4*)&xs[r * 68 + c4 * 4] = v;
        }
#pragma unroll
        for (int i = 0; i < 4; i++) {
            int p = i * 256 + tid;
            ((float4*)ws)[p] =
                *(const float4*)(W + (size_t)(kc + (p >> 4)) * 64 + (p & 15) * 4);
        }
        __syncthreads();
        mma_chunk64(xs, ws, tx, ty, acc);
        __syncthreads();
    }

    float4 bb = *(const float4*)&B[tx * 4];
#pragma unroll
    for (int i = 0; i < 4; i++) {
        int node = nodeBase + ty * 4 + i;
        if (node < NN) {
            float4 o;
            o.x = fmaxf(acc[i][0] + bb.x, 0.0f);
            o.y = fmaxf(acc[i][1] + bb.y, 0.0f);
            o.z = fmaxf(acc[i][2] + bb.z, 0.0f);
            o.w = fmaxf(acc[i][3] + bb.w, 0.0f);
            *(float4*)(Y + (size_t)node * 64 + tx * 4) = o;
            if (WRITE_G) {
                float di = dinv_of(node);
                uint2* gh = (uint2*)slot(2);  // 16 uint2 (64 halves) per row
                gh[(size_t)node * 16 + tx] =
                    pack_half4(o.x * di, o.y * di, o.z * di, o.w * di);
                *(float4*)(slot(3) + (size_t)node * 64 + tx * 4) =
                    make_float4(0.f, 0.f, 0.f, 0.f);
            }
        }
    }
}

// ---------------------------------------------------------------------------
// msg[dst] += g[src] over all edges. 16 lanes per edge (same shape as the
// proven fp32 scatter): each lane reads 4 halves (LDG.64), converts, and does
// ONE float4 RED — atomic pattern identical to the 91us fp32 version, gather
// bytes halved.
__global__ __launch_bounds__(256)
void scatter_kernel() {
    const uint2* gh = (const uint2*)slot(2);  // 16 uint2 per row (128B)
    float4* msg = (float4*)slot(3);

    int t = blockIdx.x * 256 + threadIdx.x;
    int e = t >> 4;              // grid sized exactly: e < NE always
    int lane = threadIdx.x & 15;

    int s = g_src[e];
    int d = g_dst[e];

    uint2 h = gh[(size_t)s * 16 + lane];
    float2 p0 = __half22float2(*(__half2*)&h.x);
    float2 p1 = __half22float2(*(__half2*)&h.y);
    float4 v = make_float4(p0.x, p0.y, p1.x, p1.y);

    atomicAdd(&msg[(size_t)d * 16 + lane], v);
}

// ---------------------------------------------------------------------------
// f1 = f0 - msg*dinv ; g(half) = f1*dinv ; msg = 0
__global__ __launch_bounds__(256)
void update_kernel(int f0slot, int msgslot, int f1slot) {
    int i = blockIdx.x * 256 + threadIdx.x;
    if (i < NN * 16) {
        const float4* f0 = (const float4*)slot(f0slot);
        float4* msg = (float4*)slot(msgslot);
        float4* f1 = (float4*)slot(f1slot);
        uint2* gh = (uint2*)slot(2);
        float di = dinv_of(i >> 4);
        float4 a = f0[i], m = msg[i];
        float4 f;
        f.x = a.x - m.x * di;
        f.y = a.y - m.y * di;
        f.z = a.z - m.z * di;
        f.w = a.w - m.w * di;
        f1[i] = f;
        gh[i] = pack_half4(f.x * di, f.y * di, f.z * di, f.w * di);
        msg[i] = make_float4(0.f, 0.f, 0.f, 0.f);
    }
}

// ---------------------------------------------------------------------------
// Final: f2 = f1 - msg*dinv (on the fly); hf = relu(sum_j f_j @ A_j + bm1);
// out = hf @ Wm2 + bm2. Also resets g_deg to 0 for the next graph replay.
__global__ __launch_bounds__(256)
void final_kernel(int f0slot, int f1slot, int msgslot,
                  const float* __restrict__ Wm1, const float* __restrict__ bm1,
                  const float* __restrict__ Wm2, const float* __restrict__ bm2,
                  float* __restrict__ out) {
    const float4* f0 = (const float4*)slot(f0slot);
    const float4* f1 = (const float4*)slot(f1slot);
    const float4* msg = (const float4*)slot(msgslot);

    __shared__ float fs[64 * 68];  // natural [node][k]; reused as hf[node][col]
    __shared__ float as[64 * 64];  // A_j[k][col]
    __shared__ float wm2s[128];

    int tid = threadIdx.x;
    int tx = tid & 15, ty = tid >> 4;
    int nodeBase = blockIdx.x * 64;

    if (tid < 128) wm2s[tid] = Wm2[tid];

    float acc[4][4];
#pragma unroll
    for (int i = 0; i < 4; i++)
#pragma unroll
        for (int j = 0; j < 4; j++) acc[i][j] = 0.0f;

    const float4* Wm1_4 = (const float4*)Wm1;

    for (int j = 0; j < 3; j++) {
        float c0 = COEF[j][0], c1 = COEF[j][1], c2 = COEF[j][2];
        // build A_j (64x64) in smem
#pragma unroll
        for (int i = 0; i < 4; i++) {
            int p = i * 256 + tid;  // p = k*16 + c4
            float4 w0 = Wm1_4[p];
            float4 w1 = Wm1_4[1024 + p];
            float4 w2 = Wm1_4[2048 + p];
            float4 a;
            a.x = c0 * w0.x + c1 * w1.x + c2 * w2.x;
            a.y = c0 * w0.y + c1 * w1.y + c2 * w2.y;
            a.z = c0 * w0.z + c1 * w1.z + c2 * w2.z;
            a.w = c0 * w0.w + c1 * w1.w + c2 * w2.w;
            ((float4*)as)[p] = a;
        }
        // stage f_j natural [node][k]
#pragma unroll
        for (int i = 0; i < 4; i++) {
            int p = i * 256 + tid;
            int r = p >> 4, c4 = p & 15;
            int node = nodeBase + r;
            float4 v = make_float4(0.f, 0.f, 0.f, 0.f);
            if (node < NN) {
                int idx = node * 16 + c4;
                if (j == 0) {
                    v = f0[idx];
                } else if (j == 1) {
                    v = f1[idx];
                } else {
                    float4 a1 = f1[idx], m = msg[idx];
                    float di = dinv_of(node);
                    v.x = a1.x - m.x * di;
                    v.y = a1.y - m.y * di;
                    v.z = a1.z - m.z * di;
                    v.w = a1.w - m.w * di;
                }
            }
            *(float4*)&fs[r * 68 + c4 * 4] = v;
        }
        __syncthreads();
        mma_chunk64(fs, as, tx, ty, acc);
        __syncthreads();
    }

    // bias + relu -> store hf into fs as [node][col], stride 68
    float4 bb = *(const float4*)&bm1[tx * 4];
#pragma unroll
    for (int i = 0; i < 4; i++) {
        int r = ty * 4 + i;
        float4 o;
        o.x = fmaxf(acc[i][0] + bb.x, 0.0f);
        o.y = fmaxf(acc[i][1] + bb.y, 0.0f);
        o.z = fmaxf(acc[i][2] + bb.z, 0.0f);
        o.w = fmaxf(acc[i][3] + bb.w, 0.0f);
        *(float4*)&fs[r * 68 + tx * 4] = o;
    }

    // reset degree counters for the next launch/replay (64 nodes per block)
    if (tid < 64) {
        int node = nodeBase + tid;
        if (node < NN) g_deg[node] = 0;
    }
    __syncthreads();

    // out[n][c] = bm2[c] + sum_k hf[n][k] * Wm2[k][c]
    if (tid < 128) {
        int n = tid >> 1, c = tid & 1;
        int node = nodeBase + n;
        if (node < NN) {
            float s = bm2[c];
#pragma unroll
            for (int k = 0; k < 64; k++) s += fs[n * 68 + k] * wm2s[k * 2 + c];
            out[(size_t)node * 2 + c] = s;
        }
    }
}

// ---------------------------------------------------------------------------
extern "C" void kernel_launch(void* const* d_in, const int* in_sizes, int n_in,
                              void* d_out, int out_size) {
    const float* x = (const float*)d_in[0];
    const void* ei = d_in[1];
    const float* W1 = (const float*)d_in[2];
    const float* b1 = (const float*)d_in[3];
    const float* W2 = (const float*)d_in[4];
    const float* b2 = (const float*)d_in[5];
    const float* Wm1 = (const float*)d_in[6];
    const float* bm1 = (const float*)d_in[7];
    const float* Wm2 = (const float*)d_in[8];
    const float* bm2 = (const float*)d_in[9];
    float* out = (float*)d_out;

    int nbe = (NE + 255) / 256;
    int nb = (NN + 63) / 64;   // 1563
    int nv = (NN * 16 + 255) / 256;
    int ns = (NE * 16) / 256;  // 100000 blocks

    convert_count_kernel<<<nbe, 256>>>(ei);                            // 1
    gemm_relu_kernel<128, false><<<nb, 256>>>(x, -1, W1, b1, 0);       // 2
    gemm_relu_kernel<64, true><<<nb, 256>>>(nullptr, 0, W2, b2, 1);    // 3
    scatter_kernel<<<ns, 256>>>();                                     // 4 (profiled)
    update_kernel<<<nv, 256>>>(1, 3, 0);                               // 5
    scatter_kernel<<<ns, 256>>>();                                     // 6
    final_kernel<<<nb, 256>>>(1, 0, 3, Wm1, bm1, Wm2, bm2, out);       // 7
}

// round 14
// speedup vs baseline: 1.4475x; 1.3320x over previous
#include <cuda_runtime.h>
#include <cuda_fp16.h>

#define NN 100000
#define NE 1600000

// Scratch slots, each NN*64 floats (25.6MB): 0..3
// slot 2: fp16 payload g (NN x 64 halves, 128B/row)
// slot 3: fp16 msg accumulators (NN x 64 halves, 128B/row)
__device__ float g_scratch[4ull * NN * 64];
__device__ int g_deg[NN];   // zero-init; reset by final_kernel each launch
__device__ int g_src[NE];
__device__ int g_dst[NE];

// A_j = sum_s COEF[s][j] * Wm1_s  (THETAS for D=2 folded)
__constant__ float COEF[3][3] = {
    {3.0f,  0.0f,  0.0f},
    {-3.0f, 3.0f,  0.0f},
    {0.75f, -1.5f, 0.75f}
};

__device__ __forceinline__ float* slot(int s) {
    return g_scratch + (size_t)s * (NN * 64);
}

__device__ __forceinline__ float dinv_of(int node) {
    int d = g_deg[node];
    return rsqrtf((float)(d > 0 ? d : 1));
}

// pack 4 floats -> 4 halves (uint2)
__device__ __forceinline__ uint2 pack_half4(float a, float b, float c, float d) {
    __half2 h0 = __floats2half2_rn(a, b);
    __half2 h1 = __floats2half2_rn(c, d);
    uint2 r;
    r.x = *(unsigned*)&h0;
    r.y = *(unsigned*)&h1;
    return r;
}

// ---------------------------------------------------------------------------
// Convert edge_index to int32 src/dst AND count in-degrees, one pass.
// Per-block dtype detect: int64 data has all high halves zero (indices < 1e5).
__global__ void convert_count_kernel(const void* ei) {
    __shared__ int s_is64;
    if (threadIdx.x == 0) {
        const unsigned long long* p = (const unsigned long long*)ei;
        int is64 = 1;
        for (int k = 0; k < 64; k++)
            if ((p[k] >> 32) != 0ull) { is64 = 0; break; }
        s_is64 = is64;
    }
    __syncthreads();
    int e = blockIdx.x * 256 + threadIdx.x;
    if (e < NE) {
        int s, d;
        if (s_is64) {
            const long long* p = (const long long*)ei;
            s = (int)p[e]; d = (int)p[NE + e];
        } else {
            const int* p = (const int*)ei;
            s = p[e]; d = p[NE + e];
        }
        g_src[e] = s;
        g_dst[e] = d;
        atomicAdd(&g_deg[d], 1);
    }
}

// ---------------------------------------------------------------------------
// Mainloop: 4 rows (float4 over k) x 4 cols, k grouped by 4.
// xs: [row][k] natural layout, stride 68 (conflict-free float4 staging).
__device__ __forceinline__ void mma_chunk64(
    const float* xs, const float* ws, int tx, int ty, float acc[4][4]) {
#pragma unroll
    for (int k4 = 0; k4 < 16; k4++) {
        float4 a0 = *(const float4*)&xs[(ty * 4 + 0) * 68 + k4 * 4];
        float4 a1 = *(const float4*)&xs[(ty * 4 + 1) * 68 + k4 * 4];
        float4 a2 = *(const float4*)&xs[(ty * 4 + 2) * 68 + k4 * 4];
        float4 a3 = *(const float4*)&xs[(ty * 4 + 3) * 68 + k4 * 4];
        float r0[4] = {a0.x, a0.y, a0.z, a0.w};
        float r1[4] = {a1.x, a1.y, a1.z, a1.w};
        float r2[4] = {a2.x, a2.y, a2.z, a2.w};
        float r3[4] = {a3.x, a3.y, a3.z, a3.w};
#pragma unroll
        for (int j = 0; j < 4; j++) {
            float4 b = *(const float4*)&ws[(k4 * 4 + j) * 64 + tx * 4];
            acc[0][0] += r0[j] * b.x; acc[0][1] += r0[j] * b.y;
            acc[0][2] += r0[j] * b.z; acc[0][3] += r0[j] * b.w;
            acc[1][0] += r1[j] * b.x; acc[1][1] += r1[j] * b.y;
            acc[1][2] += r1[j] * b.z; acc[1][3] += r1[j] * b.w;
            acc[2][0] += r2[j] * b.x; acc[2][1] += r2[j] * b.y;
            acc[2][2] += r2[j] * b.z; acc[2][3] += r2[j] * b.w;
            acc[3][0] += r3[j] * b.x; acc[3][1] += r3[j] * b.y;
            acc[3][2] += r3[j] * b.z; acc[3][3] += r3[j] * b.w;
        }
    }
}

// ---------------------------------------------------------------------------
// Y[N,64] = relu(X[N,K] @ W[K,64] + B), K in {64,128}
// WRITE_G: also write G = Y * dinv as fp16 (slot 2) and zero fp16 msg (slot 3).
template <int K, bool WRITE_G>
__global__ __launch_bounds__(256)
void gemm_relu_kernel(const float* __restrict__ Xext, int xslot,
                      const float* __restrict__ W, const float* __restrict__ B,
                      int yslot) {
    const float* X = Xext ? Xext : slot(xslot);
    float* Y = slot(yslot);

    __shared__ float xs[64 * 68];  // natural: xs[row][k], stride 68
    __shared__ float ws[64 * 64];  // ws[k][col]

    int tid = threadIdx.x;
    int tx = tid & 15, ty = tid >> 4;
    int nodeBase = blockIdx.x * 64;

    float acc[4][4];
#pragma unroll
    for (int i = 0; i < 4; i++)
#pragma unroll
        for (int j = 0; j < 4; j++) acc[i][j] = 0.0f;

    for (int kc = 0; kc < K; kc += 64) {
#pragma unroll
        for (int i = 0; i < 4; i++) {
            int p = i * 256 + tid;
            int r = p >> 4;
            int c4 = p & 15;
            int node = nodeBase + r;
            float4 v = make_float4(0.f, 0.f, 0.f, 0.f);
            if (node < NN)
                v = *(const float4*)(X + (size_t)node * K + kc + c4 * 4);
            *(float4*)&xs[r * 68 + c4 * 4] = v;
        }
#pragma unroll
        for (int i = 0; i < 4; i++) {
            int p = i * 256 + tid;
            ((float4*)ws)[p] =
                *(const float4*)(W + (size_t)(kc + (p >> 4)) * 64 + (p & 15) * 4);
        }
        __syncthreads();
        mma_chunk64(xs, ws, tx, ty, acc);
        __syncthreads();
    }

    float4 bb = *(const float4*)&B[tx * 4];
#pragma unroll
    for (int i = 0; i < 4; i++) {
        int node = nodeBase + ty * 4 + i;
        if (node < NN) {
            float4 o;
            o.x = fmaxf(acc[i][0] + bb.x, 0.0f);
            o.y = fmaxf(acc[i][1] + bb.y, 0.0f);
            o.z = fmaxf(acc[i][2] + bb.z, 0.0f);
            o.w = fmaxf(acc[i][3] + bb.w, 0.0f);
            *(float4*)(Y + (size_t)node * 64 + tx * 4) = o;
            if (WRITE_G) {
                float di = dinv_of(node);
                uint2* gh = (uint2*)slot(2);    // 16 uint2 (64 halves) per row
                gh[(size_t)node * 16 + tx] =
                    pack_half4(o.x * di, o.y * di, o.z * di, o.w * di);
                uint2* msgh = (uint2*)slot(3);  // zero fp16 msg
                msgh[(size_t)node * 16 + tx] = make_uint2(0u, 0u);
            }
        }
    }
}

// ---------------------------------------------------------------------------
// msg[dst] += g[src] over all edges, fp16 accumulate.
// 8 lanes per edge: each lane reads 16B of payload (LDG.128 = 8 halves) and
// issues ONE red.global.add.noftz.v4.f16x2 (16B). 8 atomic ops/edge vs 16.
__global__ __launch_bounds__(256)
void scatter_kernel() {
    const uint4* gh = (const uint4*)slot(2);  // 8 uint4 per row (128B)

    int t = blockIdx.x * 256 + threadIdx.x;
    int e = t >> 3;              // grid sized exactly: e < NE always
    int lane = threadIdx.x & 7;

    int s = g_src[e];
    int d = g_dst[e];

    uint4 a = gh[(size_t)s * 8 + lane];

    char* msgh = (char*)slot(3);
    unsigned long long addr =
        (unsigned long long)(msgh + (size_t)d * 128 + lane * 16);
    asm volatile(
        "red.global.add.noftz.v4.f16x2 [%0], {%1,%2,%3,%4};"
        :: "l"(addr), "r"(a.x), "r"(a.y), "r"(a.z), "r"(a.w)
        : "memory");
}

// ---------------------------------------------------------------------------
// f1 = f0 - msg*dinv ; g(half) = f1*dinv ; msg = 0   (msg is fp16)
__global__ __launch_bounds__(256)
void update_kernel(int f0slot, int f1slot) {
    int i = blockIdx.x * 256 + threadIdx.x;
    if (i < NN * 16) {
        const float4* f0 = (const float4*)slot(f0slot);
        float4* f1 = (float4*)slot(f1slot);
        uint2* gh = (uint2*)slot(2);
        uint2* msgh = (uint2*)slot(3);
        float di = dinv_of(i >> 4);
        uint2 mh = msgh[i];
        float2 m0 = __half22float2(*(__half2*)&mh.x);
        float2 m1 = __half22float2(*(__half2*)&mh.y);
        float4 a = f0[i];
        float4 f;
        f.x = a.x - m0.x * di;
        f.y = a.y - m0.y * di;
        f.z = a.z - m1.x * di;
        f.w = a.w - m1.y * di;
        f1[i] = f;
        gh[i] = pack_half4(f.x * di, f.y * di, f.z * di, f.w * di);
        msgh[i] = make_uint2(0u, 0u);
    }
}

// ---------------------------------------------------------------------------
// Final: f2 = f1 - msg*dinv (on the fly, msg fp16); hf = relu(sum_j f_j @ A_j
// + bm1); out = hf @ Wm2 + bm2. Also resets g_deg for the next graph replay.
__global__ __launch_bounds__(256)
void final_kernel(int f0slot, int f1slot,
                  const float* __restrict__ Wm1, const float* __restrict__ bm1,
                  const float* __restrict__ Wm2, const float* __restrict__ bm2,
                  float* __restrict__ out) {
    const float4* f0 = (const float4*)slot(f0slot);
    const float4* f1 = (const float4*)slot(f1slot);
    const uint2* msgh = (const uint2*)slot(3);

    __shared__ float fs[64 * 68];  // natural [node][k]; reused as hf[node][col]
    __shared__ float as[64 * 64];  // A_j[k][col]
    __shared__ float wm2s[128];

    int tid = threadIdx.x;
    int tx = tid & 15, ty = tid >> 4;
    int nodeBase = blockIdx.x * 64;

    if (tid < 128) wm2s[tid] = Wm2[tid];

    float acc[4][4];
#pragma unroll
    for (int i = 0; i < 4; i++)
#pragma unroll
        for (int j = 0; j < 4; j++) acc[i][j] = 0.0f;

    const float4* Wm1_4 = (const float4*)Wm1;

    for (int j = 0; j < 3; j++) {
        float c0 = COEF[j][0], c1 = COEF[j][1], c2 = COEF[j][2];
        // build A_j (64x64) in smem
#pragma unroll
        for (int i = 0; i < 4; i++) {
            int p = i * 256 + tid;  // p = k*16 + c4
            float4 w0 = Wm1_4[p];
            float4 w1 = Wm1_4[1024 + p];
            float4 w2 = Wm1_4[2048 + p];
            float4 a;
            a.x = c0 * w0.x + c1 * w1.x + c2 * w2.x;
            a.y = c0 * w0.y + c1 * w1.y + c2 * w2.y;
            a.z = c0 * w0.z + c1 * w1.z + c2 * w2.z;
            a.w = c0 * w0.w + c1 * w1.w + c2 * w2.w;
            ((float4*)as)[p] = a;
        }
        // stage f_j natural [node][k]
#pragma unroll
        for (int i = 0; i < 4; i++) {
            int p = i * 256 + tid;
            int r = p >> 4, c4 = p & 15;
            int node = nodeBase + r;
            float4 v = make_float4(0.f, 0.f, 0.f, 0.f);
            if (node < NN) {
                int idx = node * 16 + c4;
                if (j == 0) {
                    v = f0[idx];
                } else if (j == 1) {
                    v = f1[idx];
                } else {
                    float4 a1 = f1[idx];
                    uint2 mh = msgh[idx];
                    float2 m0 = __half22float2(*(__half2*)&mh.x);
                    float2 m1 = __half22float2(*(__half2*)&mh.y);
                    float di = dinv_of(node);
                    v.x = a1.x - m0.x * di;
                    v.y = a1.y - m0.y * di;
                    v.z = a1.z - m1.x * di;
                    v.w = a1.w - m1.y * di;
                }
            }
            *(float4*)&fs[r * 68 + c4 * 4] = v;
        }
        __syncthreads();
        mma_chunk64(fs, as, tx, ty, acc);
        __syncthreads();
    }

    // bias + relu -> store hf into fs as [node][col], stride 68
    float4 bb = *(const float4*)&bm1[tx * 4];
#pragma unroll
    for (int i = 0; i < 4; i++) {
        int r = ty * 4 + i;
        float4 o;
        o.x = fmaxf(acc[i][0] + bb.x, 0.0f);
        o.y = fmaxf(acc[i][1] + bb.y, 0.0f);
        o.z = fmaxf(acc[i][2] + bb.z, 0.0f);
        o.w = fmaxf(acc[i][3] + bb.w, 0.0f);
        *(float4*)&fs[r * 68 + tx * 4] = o;
    }

    // reset degree counters for the next launch/replay (64 nodes per block)
    if (tid < 64) {
        int node = nodeBase + tid;
        if (node < NN) g_deg[node] = 0;
    }
    __syncthreads();

    // out[n][c] = bm2[c] + sum_k hf[n][k] * Wm2[k][c]
    if (tid < 128) {
        int n = tid >> 1, c = tid & 1;
        int node = nodeBase + n;
        if (node < NN) {
            float s = bm2[c];
#pragma unroll
            for (int k = 0; k < 64; k++) s += fs[n * 68 + k] * wm2s[k * 2 + c];
            out[(size_t)node * 2 + c] = s;
        }
    }
}

// ---------------------------------------------------------------------------
extern "C" void kernel_launch(void* const* d_in, const int* in_sizes, int n_in,
                              void* d_out, int out_size) {
    const float* x = (const float*)d_in[0];
    const void* ei = d_in[1];
    const float* W1 = (const float*)d_in[2];
    const float* b1 = (const float*)d_in[3];
    const float* W2 = (const float*)d_in[4];
    const float* b2 = (const float*)d_in[5];
    const float* Wm1 = (const float*)d_in[6];
    const float* bm1 = (const float*)d_in[7];
    const float* Wm2 = (const float*)d_in[8];
    const float* bm2 = (const float*)d_in[9];
    float* out = (float*)d_out;

    int nbe = (NE + 255) / 256;
    int nb = (NN + 63) / 64;   // 1563
    int nv = (NN * 16 + 255) / 256;
    int ns = (NE * 8) / 256;   // 50000 blocks, exact

    convert_count_kernel<<<nbe, 256>>>(ei);                            // 1
    gemm_relu_kernel<128, false><<<nb, 256>>>(x, -1, W1, b1, 0);       // 2
    gemm_relu_kernel<64, true><<<nb, 256>>>(nullptr, 0, W2, b2, 1);    // 3
    scatter_kernel<<<ns, 256>>>();                                     // 4 (profiled)
    update_kernel<<<nv, 256>>>(1, 0);                                  // 5
    scatter_kernel<<<ns, 256>>>();                                     // 6
    final_kernel<<<nb, 256>>>(1, 0, Wm1, bm1, Wm2, bm2, out);          // 7
}